// round 15
// baseline (speedup 1.0000x reference)
#include <cuda_runtime.h>

#define H 64
#define DE 16
#define U_IN 128   // 2H

#define N_MAX 50176
#define E_MAX 802816
#define G_MAX 1024

// Scratch (static device allocations; no cudaMalloc allowed)
__device__ float g_h[N_MAX * H];        // node features (in-place per layer)
__device__ float g_p[N_MAX * H];        // h @ W1a   (dst-role partial)
__device__ float g_q[N_MAX * H];        // h @ W1b   (src-role partial)
__device__ float g_agg[N_MAX * H];      // per-node sum of relu(z1) (overwritten per layer)
__device__ int   g_deg_i[N_MAX];        // int in-degree (per launch)
__device__ int   g_cur[N_MAX];          // CSR fill cursors (per launch)
__device__ int   g_off[N_MAX + 1];      // CSR offsets
__device__ int2  g_csr[E_MAX];          // CSR slots: (src, eid)
__device__ float g_pooled[G_MAX * H];   // per-graph pooled sums (re-zeroed by final)
__device__ float g_counts[G_MAX];       // per-graph node counts (re-zeroed by final)

// ---------------------------------------------------------------------------
// CSR build (once per launch; reused by all layers)
// ---------------------------------------------------------------------------
__global__ void zero_int_kernel(int N) {
    int i = blockIdx.x * blockDim.x + threadIdx.x;
    if (i < N) { g_deg_i[i] = 0; g_cur[i] = 0; }
}

__global__ void deg_kernel(const int* __restrict__ ei, int E) {
    int e = blockIdx.x * blockDim.x + threadIdx.x;
    if (e < E) atomicAdd(&g_deg_i[ei[E + e]], 1);
}

// single-block exclusive scan of g_deg_i -> g_off  (N up to 50176)
__global__ __launch_bounds__(1024) void scan_kernel(int N) {
    __shared__ int ssum[1024];
    int t = threadIdx.x;
    int C = (N + 1023) / 1024;
    int beg = t * C;
    int end = beg + C < N ? beg + C : N;
    int s = 0;
    for (int i = beg; i < end; i++) s += g_deg_i[i];
    ssum[t] = s;
    __syncthreads();
    for (int d = 1; d < 1024; d <<= 1) {
        int v = (t >= d) ? ssum[t - d] : 0;
        __syncthreads();
        ssum[t] += v;
        __syncthreads();
    }
    int base = (t == 0) ? 0 : ssum[t - 1];
    for (int i = beg; i < end; i++) { g_off[i] = base; base += g_deg_i[i]; }
    if (t == 1023) g_off[N] = ssum[1023];
}

__global__ void fill_kernel(const int* __restrict__ ei, int E) {
    int e = blockIdx.x * blockDim.x + threadIdx.x;
    if (e >= E) return;
    int dst = ei[E + e];
    int pos = g_off[dst] + atomicAdd(&g_cur[dst], 1);
    g_csr[pos] = make_int2(ei[e], e);
}

// ---------------------------------------------------------------------------
// Per-node GEMM1 partials:  p[n] = h[n] @ W1a, q[n] = h[n] @ W1b.
// One thread per node.
// ---------------------------------------------------------------------------
__global__ __launch_bounds__(128) void prep_kernel(
    const float* __restrict__ hin, const float* __restrict__ W1, int N)
{
    extern __shared__ float smem[];
    float* sWa = smem;            // 64*64
    float* sWb = sWa + H * H;     // 64*64
    for (int i = threadIdx.x; i < H * H; i += blockDim.x) sWa[i] = W1[i];
    for (int i = threadIdx.x; i < H * H; i += blockDim.x) sWb[i] = W1[H * H + i];
    __syncthreads();

    int n = blockIdx.x * blockDim.x + threadIdx.x;
    if (n >= N) return;
    const float4* hv = reinterpret_cast<const float4*>(hin + (size_t)n * H);

    float acc[H];

    #pragma unroll
    for (int j = 0; j < H; j++) acc[j] = 0.0f;
    #pragma unroll 2
    for (int k4 = 0; k4 < 16; k4++) {
        float4 v4 = hv[k4];
        float v[4] = {v4.x, v4.y, v4.z, v4.w};
        const float* w = sWa + (k4 * 4) * H;
        #pragma unroll
        for (int u = 0; u < 4; u++)
            #pragma unroll
            for (int j = 0; j < H; j++)
                acc[j] += v[u] * w[u * H + j];
    }
    {
        float4* out = reinterpret_cast<float4*>(g_p + (size_t)n * H);
        #pragma unroll
        for (int t = 0; t < 16; t++)
            out[t] = make_float4(acc[4*t], acc[4*t+1], acc[4*t+2], acc[4*t+3]);
    }

    #pragma unroll
    for (int j = 0; j < H; j++) acc[j] = 0.0f;
    #pragma unroll 2
    for (int k4 = 0; k4 < 16; k4++) {
        float4 v4 = hv[k4];
        float v[4] = {v4.x, v4.y, v4.z, v4.w};
        const float* w = sWb + (k4 * 4) * H;
        #pragma unroll
        for (int u = 0; u < 4; u++)
            #pragma unroll
            for (int j = 0; j < H; j++)
                acc[j] += v[u] * w[u * H + j];
    }
    {
        float4* out = reinterpret_cast<float4*>(g_q + (size_t)n * H);
        #pragma unroll
        for (int t = 0; t < 16; t++)
            out[t] = make_float4(acc[4*t], acc[4*t+1], acc[4*t+2], acc[4*t+3]);
    }
}

// ---------------------------------------------------------------------------
// Edge stage via CSR: one WARP per destination node, NO atomics.
//   agg[n] = sum_{slots of n} relu(p[n] + q[src] + ea @ Wc + b1)
// Lane owns 2 output columns; Wc columns in registers; edge loop unrolled 2x.
// ---------------------------------------------------------------------------
__global__ __launch_bounds__(256) void msg_kernel(
    const float* __restrict__ ea,
    const float* __restrict__ Wc, const float* __restrict__ b1, int N)
{
    int warp = (blockIdx.x * blockDim.x + threadIdx.x) >> 5;
    int lane = threadIdx.x & 31;
    if (warp >= N) return;
    int n = warp;
    int c = 2 * lane;

    float2 wc[DE];
    #pragma unroll
    for (int u = 0; u < DE; u++)
        wc[u] = *reinterpret_cast<const float2*>(Wc + u * H + c);

    float2 bb = *reinterpret_cast<const float2*>(b1 + c);
    float2 pp = *reinterpret_cast<const float2*>(g_p + (size_t)n * H + c);
    float base0 = pp.x + bb.x;
    float base1 = pp.y + bb.y;

    float accA0 = 0.0f, accA1 = 0.0f, accB0 = 0.0f, accB1 = 0.0f;
    int kbeg = g_off[n], kend = g_off[n + 1];

    int k = kbeg;
    for (; k + 1 < kend; k += 2) {
        int2 sA = g_csr[k];
        int2 sB = g_csr[k + 1];
        float2 qA = *reinterpret_cast<const float2*>(g_q + (size_t)sA.x * H + c);
        float2 qB = *reinterpret_cast<const float2*>(g_q + (size_t)sB.x * H + c);
        const float4* eatA = reinterpret_cast<const float4*>(ea + (size_t)sA.y * DE);
        const float4* eatB = reinterpret_cast<const float4*>(ea + (size_t)sB.y * DE);
        float4 a0 = eatA[0], a1 = eatA[1], a2 = eatA[2], a3 = eatA[3];
        float4 b0 = eatB[0], b1v = eatB[1], b2 = eatB[2], b3 = eatB[3];
        float evA[DE] = {a0.x,a0.y,a0.z,a0.w, a1.x,a1.y,a1.z,a1.w,
                         a2.x,a2.y,a2.z,a2.w, a3.x,a3.y,a3.z,a3.w};
        float evB[DE] = {b0.x,b0.y,b0.z,b0.w, b1v.x,b1v.y,b1v.z,b1v.w,
                         b2.x,b2.y,b2.z,b2.w, b3.x,b3.y,b3.z,b3.w};
        float zA0 = base0 + qA.x, zA1 = base1 + qA.y;
        float zB0 = base0 + qB.x, zB1 = base1 + qB.y;
        #pragma unroll
        for (int u = 0; u < DE; u++) {
            zA0 += evA[u] * wc[u].x;  zA1 += evA[u] * wc[u].y;
            zB0 += evB[u] * wc[u].x;  zB1 += evB[u] * wc[u].y;
        }
        accA0 += fmaxf(zA0, 0.0f);  accA1 += fmaxf(zA1, 0.0f);
        accB0 += fmaxf(zB0, 0.0f);  accB1 += fmaxf(zB1, 0.0f);
    }
    if (k < kend) {
        int2 sA = g_csr[k];
        float2 qA = *reinterpret_cast<const float2*>(g_q + (size_t)sA.x * H + c);
        const float4* eatA = reinterpret_cast<const float4*>(ea + (size_t)sA.y * DE);
        float4 a0 = eatA[0], a1 = eatA[1], a2 = eatA[2], a3 = eatA[3];
        float evA[DE] = {a0.x,a0.y,a0.z,a0.w, a1.x,a1.y,a1.z,a1.w,
                         a2.x,a2.y,a2.z,a2.w, a3.x,a3.y,a3.z,a3.w};
        float zA0 = base0 + qA.x, zA1 = base1 + qA.y;
        #pragma unroll
        for (int u = 0; u < DE; u++) {
            zA0 += evA[u] * wc[u].x;  zA1 += evA[u] * wc[u].y;
        }
        accA0 += fmaxf(zA0, 0.0f);  accA1 += fmaxf(zA1, 0.0f);
    }

    *reinterpret_cast<float2*>(g_agg + (size_t)n * H + c) =
        make_float2(accA0 + accB0, accA1 + accB1);
}

// ---------------------------------------------------------------------------
// Update stage (includes deferred message GEMM2).  One thread per node.
//   a2 = agg[n] @ mW2 + deg[n]*mb2
//   t  = relu([h, a2] @ uW1 + ub1) ;  h = relu(t @ uW2 + ub2)
// On the last layer also does the mean-pool adds.
// ---------------------------------------------------------------------------
__global__ __launch_bounds__(128) void upd_kernel(
    const float* __restrict__ hin,
    const float* __restrict__ mW2, const float* __restrict__ mb2,
    const float* __restrict__ W1,  const float* __restrict__ b1,
    const float* __restrict__ W2,  const float* __restrict__ b2,
    const int* __restrict__ bidx, int do_pool, int N)
{
    extern __shared__ float smem[];
    float* sM2  = smem;                 // 64*64  (message W2)
    float* sW1  = sM2 + H * H;          // 128*64
    float* sW2  = sW1 + U_IN * H;       // 64*64
    float* smb2 = sW2 + H * H;          // 64
    float* sb1  = smb2 + H;             // 64
    float* sb2  = sb1 + H;              // 64
    for (int i = threadIdx.x; i < H * H; i += blockDim.x)    sM2[i] = mW2[i];
    for (int i = threadIdx.x; i < U_IN * H; i += blockDim.x) sW1[i] = W1[i];
    for (int i = threadIdx.x; i < H * H; i += blockDim.x)    sW2[i] = W2[i];
    if (threadIdx.x < H) {
        smb2[threadIdx.x] = mb2[threadIdx.x];
        sb1[threadIdx.x]  = b1[threadIdx.x];
        sb2[threadIdx.x]  = b2[threadIdx.x];
    }
    __syncthreads();

    int n = blockIdx.x * blockDim.x + threadIdx.x;
    if (n >= N) return;

    const float4* hv = reinterpret_cast<const float4*>(hin + (size_t)n * H);
    const float4* av = reinterpret_cast<const float4*>(g_agg + (size_t)n * H);
    float deg = (float)(g_off[n + 1] - g_off[n]);

    // phase 1: a2 = agg @ mW2 + deg*mb2
    float a2[H];
    #pragma unroll
    for (int j = 0; j < H; j++) a2[j] = deg * smb2[j];
    #pragma unroll 2
    for (int k4 = 0; k4 < 16; k4++) {
        float4 v4 = av[k4];
        float v[4] = {v4.x, v4.y, v4.z, v4.w};
        const float* w = sM2 + (k4 * 4) * H;
        #pragma unroll
        for (int u = 0; u < 4; u++)
            #pragma unroll
            for (int j = 0; j < H; j++)
                a2[j] += v[u] * w[u * H + j];
    }

    // phase 2: t = relu([h, a2] @ uW1 + ub1)
    float acc[H];
    #pragma unroll
    for (int j = 0; j < H; j++) acc[j] = sb1[j];

    #pragma unroll 2
    for (int k4 = 0; k4 < 16; k4++) {
        float4 v4 = hv[k4];
        float v[4] = {v4.x, v4.y, v4.z, v4.w};
        const float* w = sW1 + (k4 * 4) * H;
        #pragma unroll
        for (int u = 0; u < 4; u++)
            #pragma unroll
            for (int j = 0; j < H; j++)
                acc[j] += v[u] * w[u * H + j];
    }
    #pragma unroll 1
    for (int k = 0; k < H; k++) {
        float v = a2[k];
        const float* w = sW1 + (64 + k) * H;
        #pragma unroll
        for (int j = 0; j < H; j++)
            acc[j] += v * w[j];
    }

    #pragma unroll
    for (int j = 0; j < H; j++) acc[j] = fmaxf(acc[j], 0.0f);

    // phase 3: h = relu(t @ uW2 + ub2) ; optional pooling on last layer
    float* hout = g_h + (size_t)n * H;
    int b = do_pool ? bidx[n] : 0;
    if (do_pool) atomicAdd(&g_counts[b], 1.0f);
    float4* prow = reinterpret_cast<float4*>(g_pooled + (size_t)b * H);

    #pragma unroll 1
    for (int j2 = 0; j2 < H; j2 += 4) {
        float o0 = sb2[j2], o1 = sb2[j2 + 1], o2 = sb2[j2 + 2], o3 = sb2[j2 + 3];
        #pragma unroll
        for (int j = 0; j < H; j++) {
            float a = acc[j];
            float4 w = *reinterpret_cast<const float4*>(sW2 + j * H + j2);
            o0 += a * w.x; o1 += a * w.y; o2 += a * w.z; o3 += a * w.w;
        }
        float4 r;
        r.x = fmaxf(o0, 0.0f); r.y = fmaxf(o1, 0.0f);
        r.z = fmaxf(o2, 0.0f); r.w = fmaxf(o3, 0.0f);
        *reinterpret_cast<float4*>(hout + j2) = r;
        if (do_pool) atomicAdd(&prow[j2 / 4], r);
    }
}

// ---------------------------------------------------------------------------
// Head: out = relu(pooled/count @ lin1 + b1) @ lin2 + b2.  One thread/graph.
// Re-zeroes g_pooled / g_counts for the next replay.
// ---------------------------------------------------------------------------
__global__ void final_kernel(
    const float* __restrict__ l1w, const float* __restrict__ l1b,
    const float* __restrict__ l2w, const float* __restrict__ l2b,
    float* __restrict__ out, int G)
{
    __shared__ float sW[H * H];
    __shared__ float sb1[H];
    __shared__ float sw2[H];
    for (int i = threadIdx.x; i < H * H; i += blockDim.x) sW[i] = l1w[i];
    if (threadIdx.x < H) { sb1[threadIdx.x] = l1b[threadIdx.x]; sw2[threadIdx.x] = l2w[threadIdx.x]; }
    __syncthreads();

    int g = blockIdx.x * blockDim.x + threadIdx.x;
    if (g >= G) return;

    float inv = 1.0f / fmaxf(g_counts[g], 1.0f);
    float p[H];
    #pragma unroll
    for (int j = 0; j < H; j++) p[j] = g_pooled[g * H + j] * inv;

    g_counts[g] = 0.0f;
    #pragma unroll
    for (int j = 0; j < H; j++) g_pooled[g * H + j] = 0.0f;

    float o = l2b[0];
    #pragma unroll 1
    for (int j2 = 0; j2 < H; j2++) {
        float hsum = sb1[j2];
        #pragma unroll
        for (int j = 0; j < H; j++) hsum += p[j] * sW[j * H + j2];
        o += fmaxf(hsum, 0.0f) * sw2[j2];
    }
    out[g] = o;
}

// ---------------------------------------------------------------------------
extern "C" void kernel_launch(void* const* d_in, const int* in_sizes, int n_in,
                              void* d_out, int out_size)
{
    const float* x    = (const float*)d_in[0];
    const int*   ei   = (const int*)d_in[1];     // int32 (JAX x64 disabled)
    const float* ea   = (const float*)d_in[2];
    const int*   bidx = (const int*)d_in[3];     // int32
    const float* mW1 = (const float*)d_in[4];
    const float* mb1 = (const float*)d_in[5];
    const float* mW2 = (const float*)d_in[6];
    const float* mb2 = (const float*)d_in[7];
    const float* uW1 = (const float*)d_in[8];
    const float* ub1 = (const float*)d_in[9];
    const float* uW2 = (const float*)d_in[10];
    const float* ub2 = (const float*)d_in[11];
    const float* l1w = (const float*)d_in[12];
    const float* l1b = (const float*)d_in[13];
    const float* l2w = (const float*)d_in[14];
    const float* l2b = (const float*)d_in[15];

    int N = in_sizes[0] / H;
    int E = in_sizes[1] / 2;
    int L = in_sizes[5] / H;     // mb1 is (L, H)
    int G = out_size;            // output is (G, 1) float32

    const int M_IN = 2 * H + DE;  // 144: mW1 layer stride

    size_t prep_smem = (size_t)(2 * H * H) * sizeof(float);                        // 32 KB
    size_t upd_smem  = (size_t)(H * H + U_IN * H + H * H + 3 * H) * sizeof(float); // ~66 KB
    cudaFuncSetAttribute(prep_kernel, cudaFuncAttributeMaxDynamicSharedMemorySize, (int)prep_smem);
    cudaFuncSetAttribute(upd_kernel,  cudaFuncAttributeMaxDynamicSharedMemorySize, (int)upd_smem);

    float* h_ptr;
    cudaGetSymbolAddress((void**)&h_ptr, g_h);

    // CSR build (once per launch; deterministic work, bucket order arbitrary)
    zero_int_kernel<<<(N + 255) / 256, 256>>>(N);
    deg_kernel<<<(E + 255) / 256, 256>>>(ei, E);
    scan_kernel<<<1, 1024>>>(N);
    fill_kernel<<<(E + 255) / 256, 256>>>(ei, E);

    for (int l = 0; l < L; l++) {
        const float* hsrc = (l == 0) ? x : h_ptr;
        const float* W1l  = mW1 + (size_t)l * M_IN * H;
        prep_kernel<<<(N + 127) / 128, 128, prep_smem>>>(hsrc, W1l, N);
        msg_kernel<<<(N * 32 + 255) / 256, 256>>>(
            ea, W1l + (size_t)2 * H * H /* edge rows 128..143 */,
            mb1 + (size_t)l * H, N);
        upd_kernel<<<(N + 127) / 128, 128, upd_smem>>>(
            hsrc,
            mW2 + (size_t)l * H * H,    mb2 + (size_t)l * H,
            uW1 + (size_t)l * U_IN * H, ub1 + (size_t)l * H,
            uW2 + (size_t)l * H * H,    ub2 + (size_t)l * H,
            bidx, (l == L - 1) ? 1 : 0, N);
    }

    final_kernel<<<(G + 127) / 128, 128>>>(l1w, l1b, l2w, l2b, (float*)d_out, G);
}

// round 16
// speedup vs baseline: 1.4666x; 1.4666x over previous
#include <cuda_runtime.h>

#define H 64
#define DE 16
#define U_IN 128   // 2H

#define N_MAX 50176
#define E_MAX 802816
#define G_MAX 1024

// Scratch (static device allocations; no cudaMalloc allowed)
__device__ float g_h[N_MAX * H];        // node features (in-place per layer)
__device__ float g_p[N_MAX * H];        // h @ W1a   (dst-role partial)
__device__ float g_q[N_MAX * H];        // h @ W1b   (src-role partial)
__device__ float g_agg[N_MAX * H];      // per-node sum of relu(z1) (overwritten per layer)
__device__ int   g_deg_i[N_MAX];        // int in-degree (zeroed by scan for next replay)
__device__ int   g_cur[N_MAX];          // CSR fill cursors (zeroed by scan)
__device__ int   g_off[N_MAX + 1];      // CSR offsets
__device__ int   g_src[E_MAX];          // CSR: source node per slot
__device__ int   g_eid[E_MAX];          // CSR: edge id per slot
__device__ float g_pooled[G_MAX * H];   // per-graph pooled sums (re-zeroed by final)
__device__ float g_counts[G_MAX];       // per-graph node counts (re-zeroed by final)

// ---------------------------------------------------------------------------
// CSR build (once per launch; reused by all layers)
// ---------------------------------------------------------------------------
__global__ void deg_kernel(const int* __restrict__ ei, int E) {
    int e = blockIdx.x * blockDim.x + threadIdx.x;
    if (e < E) atomicAdd(&g_deg_i[ei[E + e]], 1);
}

// single-block exclusive scan of g_deg_i -> g_off  (N up to 50176).
// Also re-zeroes g_deg_i / g_cur for the next graph replay (static arrays
// start zeroed, so the invariant holds on every replay).
__global__ __launch_bounds__(1024) void scan_kernel(int N) {
    __shared__ int ssum[1024];
    int t = threadIdx.x;
    int C = (N + 1023) / 1024;
    int beg = t * C;
    int end = beg + C < N ? beg + C : N;
    int s = 0;
    for (int i = beg; i < end; i++) s += g_deg_i[i];
    ssum[t] = s;
    __syncthreads();
    for (int d = 1; d < 1024; d <<= 1) {
        int v = (t >= d) ? ssum[t - d] : 0;
        __syncthreads();
        ssum[t] += v;
        __syncthreads();
    }
    int base = (t == 0) ? 0 : ssum[t - 1];
    for (int i = beg; i < end; i++) {
        g_off[i] = base;
        base += g_deg_i[i];
        g_deg_i[i] = 0;   // restore invariant for next replay
        g_cur[i] = 0;     // cursors ready for fill
    }
    if (t == 1023) g_off[N] = ssum[1023];
}

__global__ void fill_kernel(const int* __restrict__ ei, int E) {
    int e = blockIdx.x * blockDim.x + threadIdx.x;
    if (e >= E) return;
    int dst = ei[E + e];
    int pos = g_off[dst] + atomicAdd(&g_cur[dst], 1);
    g_src[pos] = ei[e];
    g_eid[pos] = e;
}

// ---------------------------------------------------------------------------
// Per-node GEMM1 partials:  p[n] = h[n] @ W1a, q[n] = h[n] @ W1b.
// One thread per node.
// ---------------------------------------------------------------------------
__global__ __launch_bounds__(128) void prep_kernel(
    const float* __restrict__ hin, const float* __restrict__ W1, int N)
{
    extern __shared__ float smem[];
    float* sWa = smem;            // 64*64
    float* sWb = sWa + H * H;     // 64*64
    for (int i = threadIdx.x; i < H * H; i += blockDim.x) sWa[i] = W1[i];
    for (int i = threadIdx.x; i < H * H; i += blockDim.x) sWb[i] = W1[H * H + i];
    __syncthreads();

    int n = blockIdx.x * blockDim.x + threadIdx.x;
    if (n >= N) return;
    const float4* hv = reinterpret_cast<const float4*>(hin + (size_t)n * H);

    float acc[H];

    #pragma unroll
    for (int j = 0; j < H; j++) acc[j] = 0.0f;
    #pragma unroll 2
    for (int k4 = 0; k4 < 16; k4++) {
        float4 v4 = hv[k4];
        float v[4] = {v4.x, v4.y, v4.z, v4.w};
        const float* w = sWa + (k4 * 4) * H;
        #pragma unroll
        for (int u = 0; u < 4; u++)
            #pragma unroll
            for (int j = 0; j < H; j++)
                acc[j] += v[u] * w[u * H + j];
    }
    {
        float4* out = reinterpret_cast<float4*>(g_p + (size_t)n * H);
        #pragma unroll
        for (int t = 0; t < 16; t++)
            out[t] = make_float4(acc[4*t], acc[4*t+1], acc[4*t+2], acc[4*t+3]);
    }

    #pragma unroll
    for (int j = 0; j < H; j++) acc[j] = 0.0f;
    #pragma unroll 2
    for (int k4 = 0; k4 < 16; k4++) {
        float4 v4 = hv[k4];
        float v[4] = {v4.x, v4.y, v4.z, v4.w};
        const float* w = sWb + (k4 * 4) * H;
        #pragma unroll
        for (int u = 0; u < 4; u++)
            #pragma unroll
            for (int j = 0; j < H; j++)
                acc[j] += v[u] * w[u * H + j];
    }
    {
        float4* out = reinterpret_cast<float4*>(g_q + (size_t)n * H);
        #pragma unroll
        for (int t = 0; t < 16; t++)
            out[t] = make_float4(acc[4*t], acc[4*t+1], acc[4*t+2], acc[4*t+3]);
    }
}

// ---------------------------------------------------------------------------
// Edge stage via CSR: one WARP per destination node, NO atomics.
//   agg[n] = sum_{slots of n} relu(p[n] + q[src] + ea @ Wc + b1)
// Lane owns 2 output columns; Wc columns live in registers across the loop.
// (Exact R12 form — the measured-fastest configuration.)
// ---------------------------------------------------------------------------
__global__ __launch_bounds__(256) void msg_kernel(
    const float* __restrict__ ea,
    const float* __restrict__ Wc, const float* __restrict__ b1, int N)
{
    int warp = (blockIdx.x * blockDim.x + threadIdx.x) >> 5;
    int lane = threadIdx.x & 31;
    if (warp >= N) return;
    int n = warp;
    int c = 2 * lane;

    float2 wc[DE];
    #pragma unroll
    for (int u = 0; u < DE; u++)
        wc[u] = *reinterpret_cast<const float2*>(Wc + u * H + c);

    float2 bb = *reinterpret_cast<const float2*>(b1 + c);
    float2 pp = *reinterpret_cast<const float2*>(g_p + (size_t)n * H + c);
    float base0 = pp.x + bb.x;
    float base1 = pp.y + bb.y;

    float acc0 = 0.0f, acc1 = 0.0f;
    int kbeg = g_off[n], kend = g_off[n + 1];

    for (int k = kbeg; k < kend; k++) {
        int src = g_src[k];
        int e   = g_eid[k];
        float2 q = *reinterpret_cast<const float2*>(g_q + (size_t)src * H + c);
        const float4* eat = reinterpret_cast<const float4*>(ea + (size_t)e * DE);
        float4 e0 = eat[0], e1 = eat[1], e2 = eat[2], e3 = eat[3];
        float ev[DE] = {e0.x, e0.y, e0.z, e0.w,  e1.x, e1.y, e1.z, e1.w,
                        e2.x, e2.y, e2.z, e2.w,  e3.x, e3.y, e3.z, e3.w};
        float z0 = base0 + q.x;
        float z1 = base1 + q.y;
        #pragma unroll
        for (int u = 0; u < DE; u++) {
            z0 += ev[u] * wc[u].x;
            z1 += ev[u] * wc[u].y;
        }
        acc0 += fmaxf(z0, 0.0f);
        acc1 += fmaxf(z1, 0.0f);
    }

    *reinterpret_cast<float2*>(g_agg + (size_t)n * H + c) = make_float2(acc0, acc1);
}

// ---------------------------------------------------------------------------
// Update stage (includes deferred message GEMM2).  One thread per node.
//   a2 = agg[n] @ mW2 + deg[n]*mb2
//   t  = relu([h, a2] @ uW1 + ub1) ;  h = relu(t @ uW2 + ub2)
// On the last layer also does the mean-pool adds.
// ---------------------------------------------------------------------------
__global__ __launch_bounds__(128) void upd_kernel(
    const float* __restrict__ hin,
    const float* __restrict__ mW2, const float* __restrict__ mb2,
    const float* __restrict__ W1,  const float* __restrict__ b1,
    const float* __restrict__ W2,  const float* __restrict__ b2,
    const int* __restrict__ bidx, int do_pool, int N)
{
    extern __shared__ float smem[];
    float* sM2  = smem;                 // 64*64  (message W2)
    float* sW1  = sM2 + H * H;          // 128*64
    float* sW2  = sW1 + U_IN * H;       // 64*64
    float* smb2 = sW2 + H * H;          // 64
    float* sb1  = smb2 + H;             // 64
    float* sb2  = sb1 + H;              // 64
    for (int i = threadIdx.x; i < H * H; i += blockDim.x)    sM2[i] = mW2[i];
    for (int i = threadIdx.x; i < U_IN * H; i += blockDim.x) sW1[i] = W1[i];
    for (int i = threadIdx.x; i < H * H; i += blockDim.x)    sW2[i] = W2[i];
    if (threadIdx.x < H) {
        smb2[threadIdx.x] = mb2[threadIdx.x];
        sb1[threadIdx.x]  = b1[threadIdx.x];
        sb2[threadIdx.x]  = b2[threadIdx.x];
    }
    __syncthreads();

    int n = blockIdx.x * blockDim.x + threadIdx.x;
    if (n >= N) return;

    const float4* hv = reinterpret_cast<const float4*>(hin + (size_t)n * H);
    const float4* av = reinterpret_cast<const float4*>(g_agg + (size_t)n * H);
    float deg = (float)(g_off[n + 1] - g_off[n]);

    // phase 1: a2 = agg @ mW2 + deg*mb2
    float a2[H];
    #pragma unroll
    for (int j = 0; j < H; j++) a2[j] = deg * smb2[j];
    #pragma unroll 2
    for (int k4 = 0; k4 < 16; k4++) {
        float4 v4 = av[k4];
        float v[4] = {v4.x, v4.y, v4.z, v4.w};
        const float* w = sM2 + (k4 * 4) * H;
        #pragma unroll
        for (int u = 0; u < 4; u++)
            #pragma unroll
            for (int j = 0; j < H; j++)
                a2[j] += v[u] * w[u * H + j];
    }

    // phase 2: t = relu([h, a2] @ uW1 + ub1)
    float acc[H];
    #pragma unroll
    for (int j = 0; j < H; j++) acc[j] = sb1[j];

    #pragma unroll 2
    for (int k4 = 0; k4 < 16; k4++) {
        float4 v4 = hv[k4];
        float v[4] = {v4.x, v4.y, v4.z, v4.w};
        const float* w = sW1 + (k4 * 4) * H;
        #pragma unroll
        for (int u = 0; u < 4; u++)
            #pragma unroll
            for (int j = 0; j < H; j++)
                acc[j] += v[u] * w[u * H + j];
    }
    #pragma unroll 1
    for (int k = 0; k < H; k++) {
        float v = a2[k];
        const float* w = sW1 + (64 + k) * H;
        #pragma unroll
        for (int j = 0; j < H; j++)
            acc[j] += v * w[j];
    }

    #pragma unroll
    for (int j = 0; j < H; j++) acc[j] = fmaxf(acc[j], 0.0f);

    // phase 3: h = relu(t @ uW2 + ub2) ; optional pooling on last layer
    float* hout = g_h + (size_t)n * H;
    int b = do_pool ? bidx[n] : 0;
    if (do_pool) atomicAdd(&g_counts[b], 1.0f);
    float4* prow = reinterpret_cast<float4*>(g_pooled + (size_t)b * H);

    #pragma unroll 1
    for (int j2 = 0; j2 < H; j2 += 4) {
        float o0 = sb2[j2], o1 = sb2[j2 + 1], o2 = sb2[j2 + 2], o3 = sb2[j2 + 3];
        #pragma unroll
        for (int j = 0; j < H; j++) {
            float a = acc[j];
            float4 w = *reinterpret_cast<const float4*>(sW2 + j * H + j2);
            o0 += a * w.x; o1 += a * w.y; o2 += a * w.z; o3 += a * w.w;
        }
        float4 r;
        r.x = fmaxf(o0, 0.0f); r.y = fmaxf(o1, 0.0f);
        r.z = fmaxf(o2, 0.0f); r.w = fmaxf(o3, 0.0f);
        *reinterpret_cast<float4*>(hout + j2) = r;
        if (do_pool) atomicAdd(&prow[j2 / 4], r);
    }
}

// ---------------------------------------------------------------------------
// Head: out = relu(pooled/count @ lin1 + b1) @ lin2 + b2.  One thread/graph.
// Re-zeroes g_pooled / g_counts for the next replay.
// ---------------------------------------------------------------------------
__global__ void final_kernel(
    const float* __restrict__ l1w, const float* __restrict__ l1b,
    const float* __restrict__ l2w, const float* __restrict__ l2b,
    float* __restrict__ out, int G)
{
    __shared__ float sW[H * H];
    __shared__ float sb1[H];
    __shared__ float sw2[H];
    for (int i = threadIdx.x; i < H * H; i += blockDim.x) sW[i] = l1w[i];
    if (threadIdx.x < H) { sb1[threadIdx.x] = l1b[threadIdx.x]; sw2[threadIdx.x] = l2w[threadIdx.x]; }
    __syncthreads();

    int g = blockIdx.x * blockDim.x + threadIdx.x;
    if (g >= G) return;

    float inv = 1.0f / fmaxf(g_counts[g], 1.0f);
    float p[H];
    #pragma unroll
    for (int j = 0; j < H; j++) p[j] = g_pooled[g * H + j] * inv;

    g_counts[g] = 0.0f;
    #pragma unroll
    for (int j = 0; j < H; j++) g_pooled[g * H + j] = 0.0f;

    float o = l2b[0];
    #pragma unroll 1
    for (int j2 = 0; j2 < H; j2++) {
        float hsum = sb1[j2];
        #pragma unroll
        for (int j = 0; j < H; j++) hsum += p[j] * sW[j * H + j2];
        o += fmaxf(hsum, 0.0f) * sw2[j2];
    }
    out[g] = o;
}

// ---------------------------------------------------------------------------
extern "C" void kernel_launch(void* const* d_in, const int* in_sizes, int n_in,
                              void* d_out, int out_size)
{
    const float* x    = (const float*)d_in[0];
    const int*   ei   = (const int*)d_in[1];     // int32 (JAX x64 disabled)
    const float* ea   = (const float*)d_in[2];
    const int*   bidx = (const int*)d_in[3];     // int32
    const float* mW1 = (const float*)d_in[4];
    const float* mb1 = (const float*)d_in[5];
    const float* mW2 = (const float*)d_in[6];
    const float* mb2 = (const float*)d_in[7];
    const float* uW1 = (const float*)d_in[8];
    const float* ub1 = (const float*)d_in[9];
    const float* uW2 = (const float*)d_in[10];
    const float* ub2 = (const float*)d_in[11];
    const float* l1w = (const float*)d_in[12];
    const float* l1b = (const float*)d_in[13];
    const float* l2w = (const float*)d_in[14];
    const float* l2b = (const float*)d_in[15];

    int N = in_sizes[0] / H;
    int E = in_sizes[1] / 2;
    int L = in_sizes[5] / H;     // mb1 is (L, H)
    int G = out_size;            // output is (G, 1) float32

    const int M_IN = 2 * H + DE;  // 144: mW1 layer stride

    size_t prep_smem = (size_t)(2 * H * H) * sizeof(float);                        // 32 KB
    size_t upd_smem  = (size_t)(H * H + U_IN * H + H * H + 3 * H) * sizeof(float); // ~66 KB
    cudaFuncSetAttribute(prep_kernel, cudaFuncAttributeMaxDynamicSharedMemorySize, (int)prep_smem);
    cudaFuncSetAttribute(upd_kernel,  cudaFuncAttributeMaxDynamicSharedMemorySize, (int)upd_smem);

    float* h_ptr;
    cudaGetSymbolAddress((void**)&h_ptr, g_h);

    // CSR build (once per launch; deterministic work, bucket order arbitrary)
    deg_kernel<<<(E + 255) / 256, 256>>>(ei, E);
    scan_kernel<<<1, 1024>>>(N);
    fill_kernel<<<(E + 255) / 256, 256>>>(ei, E);

    for (int l = 0; l < L; l++) {
        const float* hsrc = (l == 0) ? x : h_ptr;
        const float* W1l  = mW1 + (size_t)l * M_IN * H;
        prep_kernel<<<(N + 127) / 128, 128, prep_smem>>>(hsrc, W1l, N);
        msg_kernel<<<(N * 32 + 255) / 256, 256>>>(
            ea, W1l + (size_t)2 * H * H /* edge rows 128..143 */,
            mb1 + (size_t)l * H, N);
        upd_kernel<<<(N + 127) / 128, 128, upd_smem>>>(
            hsrc,
            mW2 + (size_t)l * H * H,    mb2 + (size_t)l * H,
            uW1 + (size_t)l * U_IN * H, ub1 + (size_t)l * H,
            uW2 + (size_t)l * H * H,    ub2 + (size_t)l * H,
            bidx, (l == L - 1) ? 1 : 0, N);
    }

    final_kernel<<<(G + 127) / 128, 128>>>(l1w, l1b, l2w, l2b, (float*)d_out, G);
}